// round 1
// baseline (speedup 1.0000x reference)
#include <cuda_runtime.h>
#include <cstdint>
#include <cstring>

// Conv_39333310497378: 9-section SNN conv + maxpool(4) + threshold spikes.
// x: [16384, 1, 41, 40] f32   (per-b slab = 1640 floats; section s uses the
//                              360 contiguous floats starting at 160*s)
// W: [9, 50, 1, 6, 40] f32    (per-section weight row = 240 contiguous floats)
// out: pots [B,50,9,1] then spks [B,50,9,1], both f32, concatenated.
//
// pot(b,s,o) = max_{h<4} sum_{k<240} x[b*1640 + 160*s + 40*h + k] * W[s,o,k]
// spk = pot > 6.2 ? 1 : 0

#define B_TOTAL   16384
#define NOUT      50
#define NPAD      56          // pad N to 8 warps * 7 outputs
#define K_FLOATS  240
#define K2        120         // float2 steps along K
#define XJ2       180         // 360 floats / 2 per batch slab
#define BT        32          // batch tile per CTA (= warp lanes)
#define THREADS   256
#define XSTRIDE   (BT + 1)    // +1 float2 pad: conflict-free column loads
#define THRESH    6.2f

#define SMEM_X_F2 (XJ2 * XSTRIDE)        // 5940 float2
#define SMEM_W_F2 (NPAD * K2)            // 6720 float2
#define SMEM_BYTES ((SMEM_X_F2 + SMEM_W_F2) * 8)   // 101280 B

__global__ void __launch_bounds__(THREADS, 2)
conv_snn_kernel(const float* __restrict__ x,
                const float* __restrict__ W,
                float* __restrict__ out)
{
    const int sec = blockIdx.y;          // 0..8
    const int b0  = blockIdx.x * BT;     // batch tile base
    const int tid = threadIdx.x;

    extern __shared__ unsigned char smem_raw[];
    float2* xs = reinterpret_cast<float2*>(smem_raw);            // [XJ2][XSTRIDE]
    float2* ws = xs + SMEM_X_F2;                                  // [NPAD][K2]

    // ---- Load weights for this section (zero-pad o in [50,56)) ----
    {
        const float* Wsec = W + (size_t)sec * NOUT * K_FLOATS;
        #pragma unroll 4
        for (int idx = tid; idx < NPAD * K2; idx += THREADS) {
            int o  = idx / K2;
            int k2 = idx - o * K2;
            float2 v = make_float2(0.f, 0.f);
            if (o < NOUT)
                v = *reinterpret_cast<const float2*>(Wsec + o * K_FLOATS + 2 * k2);
            ws[o * K2 + k2] = v;
        }
    }

    // ---- Load x slab transposed: xs[j2][b] (coalesced global, padded smem) ----
    {
        #pragma unroll 4
        for (int idx = tid; idx < BT * XJ2; idx += THREADS) {
            int b  = idx / XJ2;
            int j2 = idx - b * XJ2;
            float2 v = *reinterpret_cast<const float2*>(
                x + (size_t)(b0 + b) * 1640 + sec * 160 + 2 * j2);
            xs[j2 * XSTRIDE + b] = v;
        }
    }
    __syncthreads();

    const int warp = tid >> 5;
    const int lane = tid & 31;           // lane == batch within tile
    const int o0   = warp * 7;           // 7 output channels per warp

    // f32x2 accumulators: [h][oo]; bit pattern 0 == {0.f, 0.f}
    unsigned long long acc[4][7];
    #pragma unroll
    for (int h = 0; h < 4; h++)
        #pragma unroll
        for (int oo = 0; oo < 7; oo++) acc[h][oo] = 0ull;

    const unsigned long long* xcol =
        reinterpret_cast<const unsigned long long*>(xs) + lane;
    const unsigned long long* wrow =
        reinterpret_cast<const unsigned long long*>(ws) + (size_t)o0 * K2;

    #pragma unroll 4
    for (int k2 = 0; k2 < K2; k2++) {
        unsigned long long xv[4];
        #pragma unroll
        for (int h = 0; h < 4; h++)
            xv[h] = xcol[(h * 20 + k2) * XSTRIDE];   // conflict-free LDS.64
        #pragma unroll
        for (int oo = 0; oo < 7; oo++) {
            unsigned long long wv = wrow[oo * K2 + k2];  // warp-uniform broadcast
            #pragma unroll
            for (int h = 0; h < 4; h++)
                asm("fma.rn.f32x2 %0, %1, %2, %0;"
                    : "+l"(acc[h][oo]) : "l"(xv[h]), "l"(wv));
        }
    }

    // ---- Epilogue: horizontal add, max over h, threshold, store ----
    const size_t b = (size_t)(b0 + lane);
    float* pout = out + b * 450 + sec;                    // pots[b, o, sec]
    float* sout = pout + (size_t)B_TOTAL * 450;           // spikes block

    #pragma unroll
    for (int oo = 0; oo < 7; oo++) {
        int o = o0 + oo;
        if (o < NOUT) {
            float m = -3.402823466e+38f;
            #pragma unroll
            for (int h = 0; h < 4; h++) {
                float lo = __uint_as_float((unsigned)(acc[h][oo]));
                float hi = __uint_as_float((unsigned)(acc[h][oo] >> 32));
                m = fmaxf(m, lo + hi);
            }
            pout[o * 9] = m;
            sout[o * 9] = (m > THRESH) ? 1.0f : 0.0f;
        }
    }
}

extern "C" void kernel_launch(void* const* d_in, const int* in_sizes, int n_in,
                              void* d_out, int out_size)
{
    // metadata order: x then W; be defensive via sizes (x=26.9M, W=108K elems)
    const float* x = (const float*)d_in[0];
    const float* W = (const float*)d_in[1];
    if (n_in >= 2 && in_sizes[0] < in_sizes[1]) {
        x = (const float*)d_in[1];
        W = (const float*)d_in[0];
    }
    float* out = (float*)d_out;

    cudaFuncSetAttribute(conv_snn_kernel,
                         cudaFuncAttributeMaxDynamicSharedMemorySize,
                         SMEM_BYTES);

    dim3 grid(B_TOTAL / BT, 9);   // 512 x 9 = 4608 CTAs
    conv_snn_kernel<<<grid, THREADS, SMEM_BYTES>>>(x, W, out);
}

// round 3
// speedup vs baseline: 1.0048x; 1.0048x over previous
#include <cuda_runtime.h>
#include <cstdint>
#include <cstring>

// Conv_39333310497378: 9-section SNN conv + maxpool(4) + threshold spikes.
// x: [16384, 1, 41, 40] f32   (per-b slab = 1640 floats; section s uses the
//                              360 contiguous floats starting at 160*s)
// W: [9, 50, 1, 6, 40] f32    (per-section weight row = 240 contiguous floats)
// out: pots [B,50,9,1] then spks [B,50,9,1], both f32, concatenated.
//
// pot(b,s,o) = max_{h<4} sum_{k<240} x[b*1640 + 160*s + 40*h + k] * W[s,o,k]
// spk = pot > 6.2 ? 1 : 0

#define B_TOTAL   16384
#define NOUT      50
#define NPAD      56          // pad N to 8 warps * 7 outputs
#define K_FLOATS  240
#define K2        120         // float2 steps along K
#define XJ2       180         // 360 floats / 2 per batch slab
#define BT        32          // batch tile per CTA (= warp lanes)
#define THREADS   256
#define XSTRIDE   (BT + 1)    // +1 float2 pad: conflict-free column loads
#define THRESH    6.2f

#define SMEM_X_F2 (XJ2 * XSTRIDE)        // 5940 float2
#define SMEM_W_F2 (NPAD * K2)            // 6720 float2
#define SMEM_BYTES ((SMEM_X_F2 + SMEM_W_F2) * 8)   // 101280 B

__global__ void __launch_bounds__(THREADS, 2)
conv_snn_kernel(const float* __restrict__ x,
                const float* __restrict__ W,
                float* __restrict__ out)
{
    const int sec = blockIdx.y;          // 0..8
    const int b0  = blockIdx.x * BT;     // batch tile base
    const int tid = threadIdx.x;

    extern __shared__ unsigned char smem_raw[];
    float2* xs = reinterpret_cast<float2*>(smem_raw);            // [XJ2][XSTRIDE]
    float2* ws = xs + SMEM_X_F2;                                  // [NPAD][K2]

    // ---- Load weights for this section (zero-pad o in [50,56)) ----
    {
        const float* Wsec = W + (size_t)sec * NOUT * K_FLOATS;
        #pragma unroll 4
        for (int idx = tid; idx < NPAD * K2; idx += THREADS) {
            int o  = idx / K2;
            int k2 = idx - o * K2;
            float2 v = make_float2(0.f, 0.f);
            if (o < NOUT)
                v = *reinterpret_cast<const float2*>(Wsec + o * K_FLOATS + 2 * k2);
            ws[o * K2 + k2] = v;
        }
    }

    // ---- Load x slab transposed: xs[j2][b] (coalesced global, padded smem) ----
    {
        #pragma unroll 4
        for (int idx = tid; idx < BT * XJ2; idx += THREADS) {
            int b  = idx / XJ2;
            int j2 = idx - b * XJ2;
            float2 v = *reinterpret_cast<const float2*>(
                x + (size_t)(b0 + b) * 1640 + sec * 160 + 2 * j2);
            xs[j2 * XSTRIDE + b] = v;
        }
    }
    __syncthreads();

    const int warp = tid >> 5;
    const int lane = tid & 31;           // lane == batch within tile
    const int o0   = warp * 7;           // 7 output channels per warp

    // f32x2 accumulators: [h][oo]; bit pattern 0 == {0.f, 0.f}
    unsigned long long acc[4][7];
    #pragma unroll
    for (int h = 0; h < 4; h++)
        #pragma unroll
        for (int oo = 0; oo < 7; oo++) acc[h][oo] = 0ull;

    const unsigned long long* xcol =
        reinterpret_cast<const unsigned long long*>(xs) + lane;
    const unsigned long long* wrow =
        reinterpret_cast<const unsigned long long*>(ws) + (size_t)o0 * K2;

    #pragma unroll 4
    for (int k2 = 0; k2 < K2; k2++) {
        unsigned long long xv[4];
        #pragma unroll
        for (int h = 0; h < 4; h++)
            xv[h] = xcol[(h * 20 + k2) * XSTRIDE];   // conflict-free LDS.64
        #pragma unroll
        for (int oo = 0; oo < 7; oo++) {
            unsigned long long wv = wrow[oo * K2 + k2];  // warp-uniform broadcast
            #pragma unroll
            for (int h = 0; h < 4; h++)
                asm("fma.rn.f32x2 %0, %1, %2, %0;"
                    : "+l"(acc[h][oo]) : "l"(xv[h]), "l"(wv));
        }
    }

    // ---- Epilogue: horizontal add, max over h, threshold, store ----
    const size_t b = (size_t)(b0 + lane);
    float* pout = out + b * 450 + sec;                    // pots[b, o, sec]
    float* sout = pout + (size_t)B_TOTAL * 450;           // spikes block

    #pragma unroll
    for (int oo = 0; oo < 7; oo++) {
        int o = o0 + oo;
        if (o < NOUT) {
            float m = -3.402823466e+38f;
            #pragma unroll
            for (int h = 0; h < 4; h++) {
                float lo = __uint_as_float((unsigned)(acc[h][oo]));
                float hi = __uint_as_float((unsigned)(acc[h][oo] >> 32));
                m = fmaxf(m, lo + hi);
            }
            pout[o * 9] = m;
            sout[o * 9] = (m > THRESH) ? 1.0f : 0.0f;
        }
    }
}

extern "C" void kernel_launch(void* const* d_in, const int* in_sizes, int n_in,
                              void* d_out, int out_size)
{
    // metadata order: x then W; be defensive via sizes (x=26.9M, W=108K elems)
    const float* x = (const float*)d_in[0];
    const float* W = (const float*)d_in[1];
    if (n_in >= 2 && in_sizes[0] < in_sizes[1]) {
        x = (const float*)d_in[1];
        W = (const float*)d_in[0];
    }
    float* out = (float*)d_out;

    cudaFuncSetAttribute(conv_snn_kernel,
                         cudaFuncAttributeMaxDynamicSharedMemorySize,
                         SMEM_BYTES);

    dim3 grid(B_TOTAL / BT, 9);   // 512 x 9 = 4608 CTAs
    conv_snn_kernel<<<grid, THREADS, SMEM_BYTES>>>(x, W, out);
}

// round 5
// speedup vs baseline: 1.1251x; 1.1198x over previous
#include <cuda_runtime.h>
#include <cstdint>

// Conv_39333310497378 — warp-level mma.sync tf32 (sm_103 plain target; tcgen05
// is unavailable: harness PTX target lacks the 'a' feature suffix).
//
// pot(b,s,o) = max_{h<4} sum_{k<240} x[b*1640 + 160s + 40h + k] * W[s,o,k]
// out: pots [B,50,9] then spikes [B,50,9] (f32), index b*450 + o*9 + s.

#define NB      16384
#define XSLAB   1640
#define NOUT    50
#define THRESH  6.2f

#define MT      32          // batch rows per CTA
#define NTHR    64          // 2 warps, each m16
#define XSTR    364         // x smem row stride (floats): 12*lr+lc banks, conflict-free
#define WSTR    244         // W smem row stride (floats): 20*lr+lc banks, conflict-free
#define NROWS_W 56          // padded N (7 n-frags of 8)

#define XS_FLOATS (MT * XSTR)                 // 11648
#define SMEM_TOTAL ((XS_FLOATS + NROWS_W * WSTR) * 4)   // 46592 + 54656 = 101248 B

__global__ void __launch_bounds__(NTHR, 2)
conv_mma_kernel(const float* __restrict__ x, const float* __restrict__ W,
                float* __restrict__ out)
{
  extern __shared__ float smem[];
  float* xs = smem;                       // [MT][XSTR]
  float* ws = smem + XS_FLOATS;           // [NROWS_W][WSTR]

  const int tid   = threadIdx.x;
  const int warp  = tid >> 5;
  const int lane  = tid & 31;
  const int lr    = lane >> 2;            // 0..7
  const int lc    = lane & 3;             // 0..3
  const int b0    = blockIdx.x * MT;
  const int warpM = warp * 16;

  const uint32_t* xsu = reinterpret_cast<const uint32_t*>(xs);
  const uint32_t* wsu = reinterpret_cast<const uint32_t*>(ws);

  for (int s = 0; s < 9; s++)
  {
    if (s) __syncthreads();               // previous iter's LDS done before overwrite

    // ---- W[s] -> ws, round-to-nearest tf32 (rows 50..55 left as-is, unused) ----
    {
      const float* Ws = W + (size_t)s * (NOUT * 240);
      #pragma unroll 4
      for (int i = tid; i < NOUT * 60; i += NTHR) {
        int o = i / 60, k4 = i - o * 60;
        float4 v = *reinterpret_cast<const float4*>(Ws + o * 240 + 4 * k4);
        uint4 t;
        asm("cvt.rna.tf32.f32 %0, %1;" : "=r"(t.x) : "f"(v.x));
        asm("cvt.rna.tf32.f32 %0, %1;" : "=r"(t.y) : "f"(v.y));
        asm("cvt.rna.tf32.f32 %0, %1;" : "=r"(t.z) : "f"(v.z));
        asm("cvt.rna.tf32.f32 %0, %1;" : "=r"(t.w) : "f"(v.w));
        *reinterpret_cast<uint4*>(ws + o * WSTR + 4 * k4) = t;
      }
    }
    // ---- x window [b0..b0+32) x [160s, 160s+360) -> xs, tf32-rounded ----
    {
      #pragma unroll 4
      for (int i = tid; i < MT * 90; i += NTHR) {
        int r = i / 90, q = i - r * 90;
        float4 v = *reinterpret_cast<const float4*>(
            x + (size_t)(b0 + r) * XSLAB + 160 * s + 4 * q);
        uint4 t;
        asm("cvt.rna.tf32.f32 %0, %1;" : "=r"(t.x) : "f"(v.x));
        asm("cvt.rna.tf32.f32 %0, %1;" : "=r"(t.y) : "f"(v.y));
        asm("cvt.rna.tf32.f32 %0, %1;" : "=r"(t.z) : "f"(v.z));
        asm("cvt.rna.tf32.f32 %0, %1;" : "=r"(t.w) : "f"(v.w));
        *reinterpret_cast<uint4*>(xs + r * XSTR + 4 * q) = t;
      }
    }
    __syncthreads();

    // ---- Mainloop: 30 k8-steps, accum d[h][j] (4 h-windows x 7 n-frags) ----
    float d[4][7][4];
    #pragma unroll
    for (int h = 0; h < 4; h++)
      #pragma unroll
      for (int j = 0; j < 7; j++)
        #pragma unroll
        for (int c = 0; c < 4; c++) d[h][j][c] = 0.f;

    const int arow0 = (warpM + lr) * XSTR;
    const int arow1 = (warpM + lr + 8) * XSTR;

    #pragma unroll 2
    for (int ks = 0; ks < 30; ks++)
    {
      uint32_t b[7][2];
      #pragma unroll
      for (int j = 0; j < 7; j++) {
        int n = 8 * j + lr;
        b[j][0] = wsu[n * WSTR + 8 * ks + lc];
        b[j][1] = wsu[n * WSTR + 8 * ks + lc + 4];
      }
      uint32_t a[4][4];
      #pragma unroll
      for (int h = 0; h < 4; h++) {
        int f = 40 * h + 8 * ks;
        a[h][0] = xsu[arow0 + f + lc];
        a[h][1] = xsu[arow1 + f + lc];
        a[h][2] = xsu[arow0 + f + lc + 4];
        a[h][3] = xsu[arow1 + f + lc + 4];
      }
      #pragma unroll
      for (int h = 0; h < 4; h++)
        #pragma unroll
        for (int j = 0; j < 7; j++)
          asm("mma.sync.aligned.m16n8k8.row.col.f32.tf32.tf32.f32 "
              "{%0,%1,%2,%3},{%4,%5,%6,%7},{%8,%9},{%0,%1,%2,%3};"
              : "+f"(d[h][j][0]), "+f"(d[h][j][1]),
                "+f"(d[h][j][2]), "+f"(d[h][j][3])
              : "r"(a[h][0]), "r"(a[h][1]), "r"(a[h][2]), "r"(a[h][3]),
                "r"(b[j][0]), "r"(b[j][1]));
    }

    // ---- Epilogue: max over h, threshold, store (layout verified round 1) ----
    #pragma unroll
    for (int j = 0; j < 7; j++) {
      #pragma unroll
      for (int c = 0; c < 4; c++) {
        int o = 8 * j + lc * 2 + (c & 1);
        if (o < NOUT) {
          float m = fmaxf(fmaxf(d[0][j][c], d[1][j][c]),
                          fmaxf(d[2][j][c], d[3][j][c]));
          int r = b0 + warpM + lr + ((c >> 1) << 3);
          size_t base = (size_t)r * 450 + (size_t)(o * 9 + s);
          out[base]                    = m;
          out[base + (size_t)NB * 450] = (m > THRESH) ? 1.0f : 0.0f;
        }
      }
    }
  }
}

extern "C" void kernel_launch(void* const* d_in, const int* in_sizes, int n_in,
                              void* d_out, int out_size)
{
  const float* x = (const float*)d_in[0];
  const float* W = (const float*)d_in[1];
  if (n_in >= 2 && in_sizes[0] < in_sizes[1]) {
    x = (const float*)d_in[1];
    W = (const float*)d_in[0];
  }
  float* out = (float*)d_out;

  cudaFuncSetAttribute(conv_mma_kernel,
                       cudaFuncAttributeMaxDynamicSharedMemorySize, SMEM_TOTAL);

  conv_mma_kernel<<<NB / MT, NTHR, SMEM_TOTAL>>>(x, W, out);
}

// round 9
// speedup vs baseline: 2.9939x; 2.6609x over previous
#include <cuda_runtime.h>
#include <cstdint>

// Conv_39333310497378 — fp16 mma.sync m16n8k16, f32 accumulate.
// pot(b,s,o) = max_{h<4} sum_{k<240} x[b*1640 + 160s + 40h + k] * W[s,o,k]
// out: pots [B,50,9] then spikes [B,50,9] (f32), index b*450 + o*9 + s.
// (tcgen05 unavailable: harness targets plain sm_103.)

#define NB      16384
#define XSLAB   1640
#define NOUT    50
#define THRESH  6.2f

#define MT      32            // batch rows per CTA
#define NTHR    128           // 4 warps: 2 m-tiles x 2 n-groups
#define XSTRW   188           // x row stride in fp16x2 words (188 % 32 = 28: conflict-free)
#define WSTRW   124           // W row stride in words (124 % 32 = 28)
#define WROWS   64            // padded N (rows 50..63 garbage -> discarded cols)

#define XS_WORDS (MT * XSTRW)                       // 6016
#define SMEM_BYTES ((XS_WORDS + WROWS * WSTRW) * 4) // 55808 -> 4 CTAs/SM

__global__ void __launch_bounds__(NTHR, 4)
conv_fp16_kernel(const float* __restrict__ x, const float* __restrict__ W,
                 float* __restrict__ out)
{
  extern __shared__ uint32_t sm[];
  uint32_t* xs = sm;                  // [MT][XSTRW]  fp16x2 words
  uint32_t* ws = sm + XS_WORDS;       // [WROWS][WSTRW]

  const int tid  = threadIdx.x;
  const int warp = tid >> 5, lane = tid & 31;
  const int lr   = lane >> 2, lc = lane & 3;
  const int wm   = warp & 1;          // m16 tile
  const int wn   = warp >> 1;         // n-group (o base 32*wn)
  const int b0   = blockIdx.x * MT;

  for (int s = 0; s < 9; s++)
  {
    if (s) __syncthreads();           // prior iter's LDS done before overwrite

    // ---- W[s] -> fp16 smem: 3000 float4 -> 2-word stores ----
    {
      const float* Ws = W + (size_t)s * 12000;
      #pragma unroll 4
      for (int i = tid; i < 3000; i += NTHR) {
        int r = i / 60, q = i - r * 60;
        float4 v = *reinterpret_cast<const float4*>(Ws + r * 240 + 4 * q);
        uint32_t w0, w1;
        asm("cvt.rn.f16x2.f32 %0, %1, %2;" : "=r"(w0) : "f"(v.y), "f"(v.x));
        asm("cvt.rn.f16x2.f32 %0, %1, %2;" : "=r"(w1) : "f"(v.w), "f"(v.z));
        int wi = r * WSTRW + 2 * q;
        ws[wi] = w0; ws[wi + 1] = w1;
      }
    }
    // ---- x window [b0, b0+32) x [160s, 160s+360) -> fp16 smem ----
    {
      #pragma unroll 4
      for (int i = tid; i < 2880; i += NTHR) {
        int r = i / 90, q = i - r * 90;
        float4 v = *reinterpret_cast<const float4*>(
            x + (size_t)(b0 + r) * XSLAB + 160 * s + 4 * q);
        uint32_t w0, w1;
        asm("cvt.rn.f16x2.f32 %0, %1, %2;" : "=r"(w0) : "f"(v.y), "f"(v.x));
        asm("cvt.rn.f16x2.f32 %0, %1, %2;" : "=r"(w1) : "f"(v.w), "f"(v.z));
        int wi = r * XSTRW + 2 * q;
        xs[wi] = w0; xs[wi + 1] = w1;
      }
    }
    __syncthreads();

    // ---- Mainloop: 15 k16-steps; accum d[h][j][c] ----
    float d[4][4][4];
    #pragma unroll
    for (int h = 0; h < 4; h++)
      #pragma unroll
      for (int j = 0; j < 4; j++)
        #pragma unroll
        for (int c = 0; c < 4; c++) d[h][j][c] = 0.f;

    const int ar0 = (wm * 16 + lr) * XSTRW + lc;
    const int wb0 = (wn * 32 + lr) * WSTRW + lc;

    #pragma unroll 3
    for (int ks = 0; ks < 15; ks++)
    {
      const int ko = 8 * ks;
      uint32_t b[4][2];
      #pragma unroll
      for (int j = 0; j < 4; j++) {
        int wb = wb0 + j * (8 * WSTRW) + ko;
        b[j][0] = ws[wb];
        b[j][1] = ws[wb + 4];
      }
      uint32_t a[4][4];
      #pragma unroll
      for (int h = 0; h < 4; h++) {
        int wa = ar0 + 20 * h + ko;
        a[h][0] = xs[wa];
        a[h][1] = xs[wa + 8 * XSTRW];
        a[h][2] = xs[wa + 4];
        a[h][3] = xs[wa + 8 * XSTRW + 4];
      }
      #pragma unroll
      for (int h = 0; h < 4; h++)
        #pragma unroll
        for (int j = 0; j < 4; j++)
          asm("mma.sync.aligned.m16n8k16.row.col.f32.f16.f16.f32 "
              "{%0,%1,%2,%3},{%4,%5,%6,%7},{%8,%9},{%0,%1,%2,%3};"
              : "+f"(d[h][j][0]), "+f"(d[h][j][1]),
                "+f"(d[h][j][2]), "+f"(d[h][j][3])
              : "r"(a[h][0]), "r"(a[h][1]), "r"(a[h][2]), "r"(a[h][3]),
                "r"(b[j][0]), "r"(b[j][1]));
    }

    // ---- Epilogue: max over h, threshold, store ----
    #pragma unroll
    for (int j = 0; j < 4; j++) {
      #pragma unroll
      for (int c = 0; c < 4; c++) {
        int o = wn * 32 + 8 * j + 2 * lc + (c & 1);
        if (o < NOUT) {
          float m = fmaxf(fmaxf(d[0][j][c], d[1][j][c]),
                          fmaxf(d[2][j][c], d[3][j][c]));
          int r = b0 + wm * 16 + lr + ((c >> 1) << 3);
          size_t base = (size_t)r * 450 + (size_t)(o * 9 + s);
          out[base]                    = m;
          out[base + (size_t)NB * 450] = (m > THRESH) ? 1.0f : 0.0f;
        }
      }
    }
  }
}

extern "C" void kernel_launch(void* const* d_in, const int* in_sizes, int n_in,
                              void* d_out, int out_size)
{
  const float* x = (const float*)d_in[0];
  const float* W = (const float*)d_in[1];
  if (n_in >= 2 && in_sizes[0] < in_sizes[1]) {
    x = (const float*)d_in[1];
    W = (const float*)d_in[0];
  }
  float* out = (float*)d_out;

  cudaFuncSetAttribute(conv_fp16_kernel,
                       cudaFuncAttributeMaxDynamicSharedMemorySize, SMEM_BYTES);

  conv_fp16_kernel<<<NB / MT, NTHR, SMEM_BYTES>>>(x, W, out);
}

// round 10
// speedup vs baseline: 3.4325x; 1.1465x over previous
#include <cuda_runtime.h>
#include <cstdint>

// Conv_39333310497378 — fp16 mma.sync + cp.async staging pipeline.
// pot(b,s,o) = max_{h<4} sum_{k<240} x[b*1640 + 160s + 40h + k] * W[s,o,k]
// out: pots [B,50,9] then spikes [B,50,9] (f32), index b*450 + o*9 + s.

#define NB      16384
#define XSLAB   1640
#define THRESH  6.2f
#define NTHR    128

// W fp16 scratch: [9][56 rows][124 words]; zero-init => pad rows 50..55 are 0.
#define WROWS   56
#define WSTRW   124
#define WSEC    (WROWS * WSTRW)          // 6944 words
__device__ uint32_t g_w16[9 * WSEC];     // 250 KB

// smem (32-bit words):
//   [0, 11520)        staging: 32 rows x 360 f32
//   [11520, 17280)    xbuf:    32 rows x 180 fp16x2 words (stride 180: 20lr+lc banks)
//   [17280, 24224)    wbuf:    56 rows x 124 words       (stride 124: 28lr+lc banks)
#define XB_OFF     11520
#define XSTRW      180
#define WB_OFF     17280
#define SMEM_BYTES ((WB_OFF + WSEC) * 4)   // 96896 -> 2 CTAs/SM

__global__ void prep_w_kernel(const float* __restrict__ W)
{
  int i = blockIdx.x * blockDim.x + threadIdx.x;   // 8-float chunks
  if (i >= 9 * 50 * 30) return;
  int s = i / 1500, rem = i - s * 1500;
  int o = rem / 30,  q  = rem - o * 30;
  const float* src = W + ((size_t)(s * 50 + o) * 240 + 8 * q);
  float4 v0 = *reinterpret_cast<const float4*>(src);
  float4 v1 = *reinterpret_cast<const float4*>(src + 4);
  uint4 t;
  asm("cvt.rn.f16x2.f32 %0, %1, %2;" : "=r"(t.x) : "f"(v0.y), "f"(v0.x));
  asm("cvt.rn.f16x2.f32 %0, %1, %2;" : "=r"(t.y) : "f"(v0.w), "f"(v0.z));
  asm("cvt.rn.f16x2.f32 %0, %1, %2;" : "=r"(t.z) : "f"(v1.y), "f"(v1.x));
  asm("cvt.rn.f16x2.f32 %0, %1, %2;" : "=r"(t.w) : "f"(v1.w), "f"(v1.z));
  *reinterpret_cast<uint4*>(g_w16 + s * WSEC + o * WSTRW + 4 * q) = t;
}

__device__ __forceinline__ uint32_t s2u(const void* p){
  uint32_t a;
  asm("{.reg .u64 t; cvta.to.shared.u64 t, %1; cvt.u32.u64 %0, t;}" : "=r"(a) : "l"(p));
  return a;
}
__device__ __forceinline__ void cp16(uint32_t dst, const void* src){
  asm volatile("cp.async.cg.shared.global [%0], [%1], 16;" :: "r"(dst), "l"(src) : "memory");
}

template<int JN>
__device__ __forceinline__ void core(const uint32_t* __restrict__ xb,
                                     const uint32_t* __restrict__ wb,
                                     int wm, int wn, int lr, int lc,
                                     int b0, int s, float* __restrict__ out)
{
  float d[4][JN][4];
  #pragma unroll
  for (int h = 0; h < 4; h++)
    #pragma unroll
    for (int j = 0; j < JN; j++)
      #pragma unroll
      for (int c = 0; c < 4; c++) d[h][j][c] = 0.f;

  const int ar = (wm * 16 + lr) * XSTRW + lc;
  const int wr = (wn * 32 + lr) * WSTRW + lc;

  #pragma unroll 3
  for (int ks = 0; ks < 15; ks++)
  {
    const int ko = 8 * ks;
    uint32_t b[JN][2];
    #pragma unroll
    for (int j = 0; j < JN; j++){
      b[j][0] = wb[wr + j * (8 * WSTRW) + ko];
      b[j][1] = wb[wr + j * (8 * WSTRW) + ko + 4];
    }
    uint32_t a[4][4];
    #pragma unroll
    for (int h = 0; h < 4; h++){
      int wa = ar + 20 * h + ko;
      a[h][0] = xb[wa];
      a[h][1] = xb[wa + 8 * XSTRW];
      a[h][2] = xb[wa + 4];
      a[h][3] = xb[wa + 8 * XSTRW + 4];
    }
    #pragma unroll
    for (int h = 0; h < 4; h++)
      #pragma unroll
      for (int j = 0; j < JN; j++)
        asm("mma.sync.aligned.m16n8k16.row.col.f32.f16.f16.f32 "
            "{%0,%1,%2,%3},{%4,%5,%6,%7},{%8,%9},{%0,%1,%2,%3};"
            : "+f"(d[h][j][0]), "+f"(d[h][j][1]),
              "+f"(d[h][j][2]), "+f"(d[h][j][3])
            : "r"(a[h][0]), "r"(a[h][1]), "r"(a[h][2]), "r"(a[h][3]),
              "r"(b[j][0]), "r"(b[j][1]));
  }

  #pragma unroll
  for (int j = 0; j < JN; j++)
    #pragma unroll
    for (int c = 0; c < 4; c++){
      int o = wn * 32 + 8 * j + 2 * lc + (c & 1);
      if (o < 50){
        float m = fmaxf(fmaxf(d[0][j][c], d[1][j][c]),
                        fmaxf(d[2][j][c], d[3][j][c]));
        int r = b0 + wm * 16 + lr + ((c >> 1) << 3);
        size_t base = (size_t)r * 450 + (size_t)(o * 9 + s);
        out[base]                    = m;
        out[base + (size_t)NB * 450] = (m > THRESH) ? 1.0f : 0.0f;
      }
    }
}

__global__ void __launch_bounds__(NTHR, 2)
conv_main(const float* __restrict__ x, float* __restrict__ out)
{
  extern __shared__ uint32_t sm[];
  float*    stg = reinterpret_cast<float*>(sm);   // [32][360] f32
  uint32_t* xb  = sm + XB_OFF;                    // [32][180] fp16x2
  uint32_t* wb  = sm + WB_OFF;                    // [56][124]

  const uint32_t stg_sa = s2u(stg);
  const uint32_t wb_sa  = s2u(wb);

  const int tid = threadIdx.x;
  const int warp = tid >> 5, lane = tid & 31;
  const int lr = lane >> 2, lc = lane & 3;
  const int wm = warp & 1,  wn = warp >> 1;
  const int b0 = blockIdx.x * 32;

  auto load_x = [&](int s){
    #pragma unroll 4
    for (int i = tid; i < 2880; i += NTHR){        // 16B chunks: 32 rows x 90
      int row = i / 90, c = i - row * 90;
      cp16(stg_sa + (uint32_t)(row * 360 + 4 * c) * 4,
           x + (size_t)(b0 + row) * XSLAB + 160 * s + 4 * c);
    }
  };
  auto load_w = [&](int s){
    const uint32_t* src = g_w16 + s * WSEC;
    #pragma unroll 4
    for (int i = tid; i < 1736; i += NTHR)         // 16B chunks
      cp16(wb_sa + 16u * (uint32_t)i, src + 4 * i);
  };

  load_x(0);
  load_w(0);
  asm volatile("cp.async.commit_group;" ::: "memory");

  for (int s = 0; s < 9; s++)
  {
    asm volatile("cp.async.wait_group 0;" ::: "memory");
    __syncthreads();                 // staging(s) + wbuf(s) visible to all

    // convert staging f32 -> xbuf fp16 (vectorized, conflict-free)
    #pragma unroll 4
    for (int i = tid; i < 2880; i += NTHR){
      int row = i / 90, p = i - row * 90;          // p = fp16x2 word pair
      float4 v = *reinterpret_cast<const float4*>(stg + row * 360 + 4 * p);
      uint32_t w0, w1;
      asm("cvt.rn.f16x2.f32 %0, %1, %2;" : "=r"(w0) : "f"(v.y), "f"(v.x));
      asm("cvt.rn.f16x2.f32 %0, %1, %2;" : "=r"(w1) : "f"(v.w), "f"(v.z));
      *reinterpret_cast<uint2*>(xb + row * XSTRW + 2 * p) = make_uint2(w0, w1);
    }
    __syncthreads();                 // xbuf ready; staging free

    if (s < 8){                      // x(s+1) overlaps compute(s)
      load_x(s + 1);
      asm volatile("cp.async.commit_group;" ::: "memory");
    }

    if (wn == 0) core<4>(xb, wb, wm, 0, lr, lc, b0, s, out);
    else         core<3>(xb, wb, wm, 1, lr, lc, b0, s, out);

    __syncthreads();                 // all warps done with wbuf
    if (s < 8){
      load_w(s + 1);
      asm volatile("cp.async.commit_group;" ::: "memory");
    }
  }
}

extern "C" void kernel_launch(void* const* d_in, const int* in_sizes, int n_in,
                              void* d_out, int out_size)
{
  const float* x = (const float*)d_in[0];
  const float* W = (const float*)d_in[1];
  if (n_in >= 2 && in_sizes[0] < in_sizes[1]) {
    x = (const float*)d_in[1];
    W = (const float*)d_in[0];
  }
  float* out = (float*)d_out;

  prep_w_kernel<<<54, 256>>>(W);     // 13500 chunks of 8 floats

  cudaFuncSetAttribute(conv_main,
                       cudaFuncAttributeMaxDynamicSharedMemorySize, SMEM_BYTES);
  conv_main<<<NB / 32, NTHR, SMEM_BYTES>>>(x, out);
}